// round 1
// baseline (speedup 1.0000x reference)
#include <cuda_runtime.h>
#include <math.h>

// Problem dims
constexpr int B_ = 8;
constexpr int N_ = 1024;
constexpr int D_ = 256;

// ---------------- scratch (__device__ globals; no allocation) ----------------
__device__ float g_t[(size_t)B_ * N_ * D_];          // x @ U^T            [8192,256]
__device__ float g_xs[(size_t)B_ * N_ * 2 * D_];     // spectral outputs   [8192,512] cols k*256+j
__device__ float g_U12T[2 * D_ * D_];                // [512,256]: row k*256+j, col d = |S_k[d]|*U[d,j]
__device__ float g_pos[(size_t)N_ * N_];             // pos softmax        [1024,1024]
__device__ float g_scores[(size_t)B_ * 2 * N_ * N_]; // patch logits*scale [b,k,n,m]
__device__ float g_attn[(size_t)B_ * N_ * N_];       // selected attn rows
__device__ float g_yT[(size_t)B_ * D_ * N_];         // y transposed [b,j,m]

// ---------------- helpers ----------------
__device__ __forceinline__ float blk_max(float v, volatile float* sm) {
    #pragma unroll
    for (int o = 16; o > 0; o >>= 1) v = fmaxf(v, __shfl_xor_sync(0xffffffffu, v, o));
    if ((threadIdx.x & 31) == 0) sm[threadIdx.x >> 5] = v;
    __syncthreads();
    float r = sm[0];
    #pragma unroll
    for (int i = 1; i < 8; i++) r = fmaxf(r, sm[i]);
    __syncthreads();
    return r;
}

__device__ __forceinline__ float blk_sum(float v, volatile float* sm) {
    #pragma unroll
    for (int o = 16; o > 0; o >>= 1) v += __shfl_xor_sync(0xffffffffu, v, o);
    if ((threadIdx.x & 31) == 0) sm[threadIdx.x >> 5] = v;
    __syncthreads();
    float r = sm[0];
    #pragma unroll
    for (int i = 1; i < 8; i++) r += sm[i];
    __syncthreads();
    return r;
}

// ---------------- NT GEMM: C[m,n] = alpha * sum_k A[m,k]*Bm[n,k] ----------------
// BM=BN=64, BK=16, 256 threads, 4x4 micro-tile. All dims assumed divisible.
__device__ __forceinline__ void gemm_nt_64(
    const float* __restrict__ A, int lda,
    const float* __restrict__ Bm, int ldb,
    float* __restrict__ C, int ldc,
    int K, float alpha)
{
    constexpr int BM = 64, BN = 64, BK = 16, PAD = 4;
    __shared__ float As[BK][BM + PAD];
    __shared__ float Bs[BK][BN + PAD];

    const int tid = threadIdx.x;
    const int m0 = blockIdx.y * BM;
    const int n0 = blockIdx.x * BN;

    const int lr = tid >> 2;          // 0..63 : row within tile
    const int lc = (tid & 3) * 4;     // 0,4,8,12 : k offset (float4)
    const int tr = (tid >> 4) * 4;    // micro-tile row origin
    const int tc = (tid & 15) * 4;    // micro-tile col origin

    float acc[4][4] = {};

    const float* aP = A + (size_t)(m0 + lr) * lda + lc;
    const float* bP = Bm + (size_t)(n0 + lr) * ldb + lc;

    for (int kk = 0; kk < K; kk += BK) {
        float4 av = *(const float4*)(aP + kk);
        float4 bv = *(const float4*)(bP + kk);
        __syncthreads();
        As[lc + 0][lr] = av.x; As[lc + 1][lr] = av.y;
        As[lc + 2][lr] = av.z; As[lc + 3][lr] = av.w;
        Bs[lc + 0][lr] = bv.x; Bs[lc + 1][lr] = bv.y;
        Bs[lc + 2][lr] = bv.z; Bs[lc + 3][lr] = bv.w;
        __syncthreads();
        #pragma unroll
        for (int k2 = 0; k2 < BK; k2++) {
            float4 a = *(const float4*)&As[k2][tr];
            float4 b = *(const float4*)&Bs[k2][tc];
            acc[0][0] += a.x * b.x; acc[0][1] += a.x * b.y; acc[0][2] += a.x * b.z; acc[0][3] += a.x * b.w;
            acc[1][0] += a.y * b.x; acc[1][1] += a.y * b.y; acc[1][2] += a.y * b.z; acc[1][3] += a.y * b.w;
            acc[2][0] += a.z * b.x; acc[2][1] += a.z * b.y; acc[2][2] += a.z * b.z; acc[2][3] += a.z * b.w;
            acc[3][0] += a.w * b.x; acc[3][1] += a.w * b.y; acc[3][2] += a.w * b.z; acc[3][3] += a.w * b.w;
        }
    }

    #pragma unroll
    for (int i = 0; i < 4; i++) {
        float4 o;
        o.x = alpha * acc[i][0]; o.y = alpha * acc[i][1];
        o.z = alpha * acc[i][2]; o.w = alpha * acc[i][3];
        *(float4*)(C + (size_t)(m0 + tr + i) * ldc + n0 + tc) = o;
    }
}

// ---------------- kernels ----------------

// U12T[k*256+j][d] = |S_k[d]| * U[d][j]
__global__ void k_prep_u(const float* __restrict__ U,
                         const float* __restrict__ S1,
                         const float* __restrict__ S2) {
    int idx = blockIdx.x * blockDim.x + threadIdx.x;  // 512*256
    int r = idx >> 8;        // 0..511
    int d = idx & 255;
    int k = r >> 8;
    int j = r & 255;
    float s = fabsf(k ? S2[d] : S1[d]);
    g_U12T[idx] = s * U[d * 256 + j];
}

// yT[b][j][m] = y[b][m][j]
__global__ void k_transpose_y(const float* __restrict__ y) {
    __shared__ float tile[32][33];
    int b = blockIdx.z;
    int m0 = blockIdx.y * 32, j0 = blockIdx.x * 32;
    int tx = threadIdx.x, ty = threadIdx.y;   // 32 x 8
    #pragma unroll
    for (int i = ty; i < 32; i += 8)
        tile[i][tx] = y[((size_t)b * N_ + m0 + i) * D_ + j0 + tx];
    __syncthreads();
    #pragma unroll
    for (int i = ty; i < 32; i += 8)
        g_yT[((size_t)b * D_ + j0 + i) * N_ + m0 + tx] = tile[tx][i];
}

__global__ void k_gemm_t(const float* __restrict__ x, const float* __restrict__ U) {
    gemm_nt_64(x, D_, U, D_, g_t, D_, D_, 1.0f);
}

__global__ void k_gemm_xs() {
    gemm_nt_64(g_t, D_, g_U12T, D_, g_xs, 2 * D_, D_, 1.0f);
}

__global__ void k_gemm_scores(const float* __restrict__ y) {
    int z = blockIdx.z;           // b*2 + k
    int b = z >> 1, k = z & 1;
    gemm_nt_64(g_xs + (size_t)b * N_ * (2 * D_) + k * D_, 2 * D_,
               y + (size_t)b * N_ * D_, D_,
               g_scores + (size_t)z * N_ * N_, N_,
               D_, 0.0625f /* D^-0.5 */);
}

__global__ void k_gemm_out(float* __restrict__ out) {
    int b = blockIdx.z;
    gemm_nt_64(g_attn + (size_t)b * N_ * N_, N_,
               g_yT + (size_t)b * D_ * N_, N_,
               out + (size_t)b * N_ * D_, D_,
               N_, 1.0f);
}

// pos_score[n][m] = softmax_m( -|p_temp| * sum_c coords[n,m,c]*pos_emb[n,c] )
__global__ void k_pos(const float* __restrict__ coords,
                      const float* __restrict__ pos_emb,
                      const float* __restrict__ p_temp) {
    __shared__ float pe[6];
    __shared__ float sm[8];
    int n = blockIdx.x;
    int t = threadIdx.x;     // 256
    if (t < 6) pe[t] = pos_emb[n * 6 + t];
    __syncthreads();
    float pt = -fabsf(p_temp[0]);
    float lg[4];
    float lmax = -1e30f;
    #pragma unroll
    for (int i = 0; i < 4; i++) {
        int m = i * 256 + t;
        const float* c = coords + ((size_t)n * N_ + m) * 6;
        float acc = c[0] * pe[0] + c[1] * pe[1] + c[2] * pe[2]
                  + c[3] * pe[3] + c[4] * pe[4] + c[5] * pe[5];
        lg[i] = pt * acc;
        lmax = fmaxf(lmax, lg[i]);
    }
    float mx = blk_max(lmax, sm);
    float lsum = 0.f;
    #pragma unroll
    for (int i = 0; i < 4; i++) { lg[i] = __expf(lg[i] - mx); lsum += lg[i]; }
    float s = blk_sum(lsum, sm);
    float inv = 1.0f / s;
    #pragma unroll
    for (int i = 0; i < 4; i++)
        g_pos[(size_t)n * N_ + i * 256 + t] = lg[i] * inv;
}

// Per (b,n): softmax both branches, blend with pos, entropy, route, write selected row + heat.
__global__ void k_mix(const float* __restrict__ gating,
                      const float* __restrict__ h_temp,
                      float* __restrict__ heat) {
    __shared__ float sm[8];
    int bn = blockIdx.x;             // b*1024 + n
    int b = bn >> 10;
    int n = bn & (N_ - 1);
    int t = threadIdx.x;             // 256

    size_t base0 = ((size_t)(b * 2 + 0) * N_ + n) * N_;
    size_t base1 = ((size_t)(b * 2 + 1) * N_ + n) * N_;

    float s0[4], s1[4], pp[4];
    float lm0 = -1e30f, lm1 = -1e30f;
    #pragma unroll
    for (int i = 0; i < 4; i++) {
        int m = i * 256 + t;
        s0[i] = g_scores[base0 + m];
        s1[i] = g_scores[base1 + m];
        pp[i] = g_pos[(size_t)n * N_ + m];
        lm0 = fmaxf(lm0, s0[i]);
        lm1 = fmaxf(lm1, s1[i]);
    }
    float mx0 = blk_max(lm0, sm);
    float mx1 = blk_max(lm1, sm);

    float ls0 = 0.f, ls1 = 0.f;
    #pragma unroll
    for (int i = 0; i < 4; i++) {
        s0[i] = __expf(s0[i] - mx0); ls0 += s0[i];
        s1[i] = __expf(s1[i] - mx1); ls1 += s1[i];
    }
    float sum0 = blk_sum(ls0, sm);
    float sum1 = blk_sum(ls1, sm);
    float inv0 = 1.0f / sum0, inv1 = 1.0f / sum1;

    float g = 1.0f / (1.0f + __expf(-gating[0]));
    float og = 1.0f - g;

    float p0[4], p1[4];
    float le0 = 0.f, le1 = 0.f;
    #pragma unroll
    for (int i = 0; i < 4; i++) {
        p0[i] = og * s0[i] * inv0 + g * pp[i];
        p1[i] = og * s1[i] * inv1 + g * pp[i];
        le0 -= p0[i] * __logf(p0[i] + 1e-8f);
        le1 -= p1[i] * __logf(p1[i] + 1e-8f);
    }
    float ent0 = blk_sum(le0, sm);
    float ent1 = blk_sum(le1, sm);

    float ht = h_temp[0];
    float hm0 = 2.0f - 2.0f / (1.0f + __expf(-ht * ent0));
    float hm1 = 2.0f - 2.0f / (1.0f + __expf(-ht * ent1));
    int sel = (hm0 >= hm1) ? 0 : 1;

    #pragma unroll
    for (int i = 0; i < 4; i++)
        g_attn[(size_t)bn * N_ + i * 256 + t] = sel ? p1[i] : p0[i];

    if (t == 0) heat[bn] = sel ? hm1 : hm0;
}

// ---------------- launch ----------------
extern "C" void kernel_launch(void* const* d_in, const int* in_sizes, int n_in,
                              void* d_out, int out_size) {
    const float* x       = (const float*)d_in[0];
    const float* y       = (const float*)d_in[1];
    const float* coords  = (const float*)d_in[2];
    const float* U       = (const float*)d_in[3];
    const float* S1      = (const float*)d_in[4];
    const float* S2      = (const float*)d_in[5];
    const float* gating  = (const float*)d_in[6];
    const float* h_temp  = (const float*)d_in[7];
    const float* p_temp  = (const float*)d_in[8];
    const float* pos_emb = (const float*)d_in[9];

    float* out  = (float*)d_out;
    float* heat = out + (size_t)B_ * N_ * D_;

    // prep
    k_prep_u<<<(2 * D_ * D_) / 256, 256>>>(U, S1, S2);
    k_transpose_y<<<dim3(D_ / 32, N_ / 32, B_), dim3(32, 8)>>>(y);
    k_pos<<<N_, 256>>>(coords, pos_emb, p_temp);

    // spectral: t = x@U^T ; xs = t@U12T^T
    k_gemm_t<<<dim3(D_ / 64, (B_ * N_) / 64), 256>>>(x, U);
    k_gemm_xs<<<dim3((2 * D_) / 64, (B_ * N_) / 64), 256>>>();

    // patch logits (scaled)
    k_gemm_scores<<<dim3(N_ / 64, N_ / 64, B_ * 2), 256>>>(y);

    // softmax/blend/entropy/route
    k_mix<<<B_ * N_, 256>>>(gating, h_temp, heat);

    // out = attn_sel @ y
    k_gemm_out<<<dim3(D_ / 64, N_ / 64, B_), 256>>>(out);
}